// round 1
// baseline (speedup 1.0000x reference)
#include <cuda_runtime.h>
#include <cstdint>

// Sinkhorn on B x 64 x 64 matrices, linear domain, warp-per-matrix,
// register-resident tiles with f32x2 packed math.

typedef unsigned long long u64;
#define FULLMASK 0xffffffffu

__device__ __forceinline__ u64 pk2(float lo, float hi){
    u64 r; asm("mov.b64 %0, {%1, %2};" : "=l"(r) : "f"(lo), "f"(hi)); return r;
}
__device__ __forceinline__ void up2(u64 p, float& lo, float& hi){
    asm("mov.b64 {%0, %1}, %2;" : "=f"(lo), "=f"(hi) : "l"(p));
}
__device__ __forceinline__ u64 addx2(u64 a, u64 b){
    u64 r; asm("add.rn.f32x2 %0, %1, %2;" : "=l"(r) : "l"(a), "l"(b)); return r;
}
__device__ __forceinline__ u64 mulx2(u64 a, u64 b){
    u64 r; asm("mul.rn.f32x2 %0, %1, %2;" : "=l"(r) : "l"(a), "l"(b)); return r;
}
__device__ __forceinline__ float frcp(float x){
    float r; asm("rcp.approx.f32 %0, %1;" : "=f"(r) : "f"(x)); return r;
}
__device__ __forceinline__ float fex2(float x){
    float r; asm("ex2.approx.f32 %0, %1;" : "=f"(r) : "f"(x)); return r;
}

// Precomputed softplus(-gamma) * (1/temp) * log2(e), shared by all batches.
__device__ float d_gp2[64 * 64];

__global__ void prep_kernel(const float* __restrict__ gamma){
    int i = blockIdx.x * blockDim.x + threadIdx.x;
    if (i < 64 * 64){
        float g = gamma[i];
        // softplus(-g), numerically stable both signs
        float sp = (g > 0.f) ? log1pf(expf(-g)) : (-g + log1pf(expf(g)));
        d_gp2[i] = sp * 14.4269504088896341f;   // * 10 (1/temp) * log2(e)
    }
}

__global__ void __launch_bounds__(256, 1) sinkhorn_kernel(
        const float* __restrict__ noise, float* __restrict__ out, int B){
    int gw = (int)((blockIdx.x * blockDim.x + threadIdx.x) >> 5);  // matrix id
    if (gw >= B) return;
    int lane = threadIdx.x & 31;
    int tj = lane & 7;        // column group (8 groups of 8 cols)
    int ti = lane >> 3;       // row group    (4 groups of 16 rows)
    int row0 = ti * 16, col0 = tj * 8;

    const float* np = noise + ((size_t)gw * 64 + row0) * 64 + col0;
    const float* gp = d_gp2 + row0 * 64 + col0;
    const float KS = 14.4269504088896341f;     // 10 * log2(e)

    // Tile: 16 rows x 8 cols per lane, stored as 4 packed f32x2 per row.
    u64 a[16][4];
    float m[16];

    // ---- load, scale into log2 domain, per-row max (in-thread part) ----
    #pragma unroll
    for (int r = 0; r < 16; ++r){
        float4 n0 = *(const float4*)(np + (size_t)r * 64);
        float4 n1 = *(const float4*)(np + (size_t)r * 64 + 4);
        float4 g0 = *(const float4*)(gp + r * 64);
        float4 g1 = *(const float4*)(gp + r * 64 + 4);
        float x0 = fmaf(n0.x, KS, g0.x);
        float x1 = fmaf(n0.y, KS, g0.y);
        float x2 = fmaf(n0.z, KS, g0.z);
        float x3 = fmaf(n0.w, KS, g0.w);
        float x4 = fmaf(n1.x, KS, g1.x);
        float x5 = fmaf(n1.y, KS, g1.y);
        float x6 = fmaf(n1.z, KS, g1.z);
        float x7 = fmaf(n1.w, KS, g1.w);
        a[r][0] = pk2(x0, x1);
        a[r][1] = pk2(x2, x3);
        a[r][2] = pk2(x4, x5);
        a[r][3] = pk2(x6, x7);
        m[r] = fmaxf(fmaxf(fmaxf(x0, x1), fmaxf(x2, x3)),
                     fmaxf(fmaxf(x4, x5), fmaxf(x6, x7)));
    }
    // ---- row max across lanes, then P = exp2(la2 - rowmax)  (in (0,1]) ----
    #pragma unroll
    for (int r = 0; r < 16; ++r){
        float mm = m[r];
        mm = fmaxf(mm, __shfl_xor_sync(FULLMASK, mm, 1));
        mm = fmaxf(mm, __shfl_xor_sync(FULLMASK, mm, 2));
        mm = fmaxf(mm, __shfl_xor_sync(FULLMASK, mm, 4));
        u64 nm = pk2(-mm, -mm);
        #pragma unroll
        for (int p = 0; p < 4; ++p){
            u64 t = addx2(a[r][p], nm);
            float u, v; up2(t, u, v);
            a[r][p] = pk2(fex2(u), fex2(v));
        }
    }

    // ---- 50 Sinkhorn iterations: row normalize, then col normalize ----
    // (the first row-normalization completes the stable logsumexp division:
    //  exp(la - LSE) == exp2(la2 - m) / sum(exp2(la2 - m)) )
    #pragma unroll 1
    for (int it = 0; it < 50; ++it){
        // row normalize: sums over 8 in-thread cols, butterfly across tj
        #pragma unroll
        for (int rp = 0; rp < 8; ++rp){
            int r0 = 2 * rp, r1 = r0 + 1;
            u64 s0 = addx2(addx2(a[r0][0], a[r0][1]), addx2(a[r0][2], a[r0][3]));
            u64 s1 = addx2(addx2(a[r1][0], a[r1][1]), addx2(a[r1][2], a[r1][3]));
            float s0x, s0y, s1x, s1y;
            up2(s0, s0x, s0y); up2(s1, s1x, s1y);
            u64 pr = pk2(s0x + s0y, s1x + s1y);          // two rows packed
            pr = addx2(pr, __shfl_xor_sync(FULLMASK, pr, 1));
            pr = addx2(pr, __shfl_xor_sync(FULLMASK, pr, 2));
            pr = addx2(pr, __shfl_xor_sync(FULLMASK, pr, 4));
            float rs0, rs1; up2(pr, rs0, rs1);
            float ir0 = frcp(rs0), ir1 = frcp(rs1);
            u64 rr0 = pk2(ir0, ir0), rr1 = pk2(ir1, ir1);
            #pragma unroll
            for (int p = 0; p < 4; ++p){
                a[r0][p] = mulx2(a[r0][p], rr0);
                a[r1][p] = mulx2(a[r1][p], rr1);
            }
        }
        // col normalize: tree over 16 in-thread rows, butterfly across ti
        #pragma unroll
        for (int p = 0; p < 4; ++p){
            u64 s01 = addx2(a[0][p],  a[1][p]);
            u64 s23 = addx2(a[2][p],  a[3][p]);
            u64 s45 = addx2(a[4][p],  a[5][p]);
            u64 s67 = addx2(a[6][p],  a[7][p]);
            u64 s89 = addx2(a[8][p],  a[9][p]);
            u64 sab = addx2(a[10][p], a[11][p]);
            u64 scd = addx2(a[12][p], a[13][p]);
            u64 sef = addx2(a[14][p], a[15][p]);
            u64 q0 = addx2(s01, s23);
            u64 q1 = addx2(s45, s67);
            u64 q2 = addx2(s89, sab);
            u64 q3 = addx2(scd, sef);
            u64 cs = addx2(addx2(q0, q1), addx2(q2, q3));
            cs = addx2(cs, __shfl_xor_sync(FULLMASK, cs, 8));
            cs = addx2(cs, __shfl_xor_sync(FULLMASK, cs, 16));
            float cx, cy; up2(cs, cx, cy);
            u64 cr = pk2(frcp(cx), frcp(cy));
            #pragma unroll
            for (int r = 0; r < 16; ++r)
                a[r][p] = mulx2(a[r][p], cr);
        }
    }

    // ---- store (already linear domain; no final exp needed) ----
    float* op = out + ((size_t)gw * 64 + row0) * 64 + col0;
    #pragma unroll
    for (int r = 0; r < 16; ++r){
        float x0, x1, x2, x3, x4, x5, x6, x7;
        up2(a[r][0], x0, x1); up2(a[r][1], x2, x3);
        up2(a[r][2], x4, x5); up2(a[r][3], x6, x7);
        *(float4*)(op + (size_t)r * 64)     = make_float4(x0, x1, x2, x3);
        *(float4*)(op + (size_t)r * 64 + 4) = make_float4(x4, x5, x6, x7);
    }
}

extern "C" void kernel_launch(void* const* d_in, const int* in_sizes, int n_in,
                              void* d_out, int out_size) {
    const float* gamma = (const float*)d_in[0];   // [64,64] fp32
    const float* noise = (const float*)d_in[1];   // [B,64,64] fp32
    float* out = (float*)d_out;                   // [B,64,64] fp32
    int B = in_sizes[1] / (64 * 64);

    prep_kernel<<<16, 256>>>(gamma);
    int blocks = (B * 32 + 255) / 256;            // one warp per matrix
    sinkhorn_kernel<<<blocks, 256>>>(noise, out, B);
}

// round 2
// speedup vs baseline: 1.0931x; 1.0931x over previous
#include <cuda_runtime.h>
#include <cstdint>

// Sinkhorn on B x 64 x 64 matrices, scaling-vector (u/v) form.
// K = exp2(scaled log-alpha - rowmax) stays frozen in registers;
// iterate r = 1/(K c), c = 1/(K^T r); output = diag(r) K diag(c).

typedef unsigned long long u64;
#define FULLMASK 0xffffffffu

__device__ __forceinline__ u64 pk2(float lo, float hi){
    u64 r; asm("mov.b64 %0, {%1, %2};" : "=l"(r) : "f"(lo), "f"(hi)); return r;
}
__device__ __forceinline__ void up2(u64 p, float& lo, float& hi){
    asm("mov.b64 {%0, %1}, %2;" : "=f"(lo), "=f"(hi) : "l"(p));
}
__device__ __forceinline__ u64 addx2(u64 a, u64 b){
    u64 r; asm("add.rn.f32x2 %0, %1, %2;" : "=l"(r) : "l"(a), "l"(b)); return r;
}
__device__ __forceinline__ u64 mulx2(u64 a, u64 b){
    u64 r; asm("mul.rn.f32x2 %0, %1, %2;" : "=l"(r) : "l"(a), "l"(b)); return r;
}
__device__ __forceinline__ u64 fmax2(u64 a, u64 b, u64 c){
    u64 r; asm("fma.rn.f32x2 %0, %1, %2, %3;" : "=l"(r) : "l"(a), "l"(b), "l"(c)); return r;
}
__device__ __forceinline__ float frcp(float x){
    float r; asm("rcp.approx.f32 %0, %1;" : "=f"(r) : "f"(x)); return r;
}
__device__ __forceinline__ float fex2(float x){
    float r; asm("ex2.approx.f32 %0, %1;" : "=f"(r) : "f"(x)); return r;
}
__device__ __forceinline__ u64 shfl64(u64 v, int m){
    return __shfl_xor_sync(FULLMASK, v, m);
}

// Precomputed softplus(-gamma) * (1/temp) * log2(e), shared by all batches.
__device__ float d_gp2[64 * 64];

__global__ void prep_kernel(const float* __restrict__ gamma){
    int i = blockIdx.x * blockDim.x + threadIdx.x;
    if (i < 64 * 64){
        float g = gamma[i];
        float sp = (g > 0.f) ? log1pf(expf(-g)) : (-g + log1pf(expf(g)));
        d_gp2[i] = sp * 14.4269504088896341f;   // * 10 (1/temp) * log2(e)
    }
}

__global__ void __launch_bounds__(384, 1) sinkhorn_kernel(
        const float* __restrict__ noise, float* __restrict__ out, int B){
    int gw = (int)((blockIdx.x * blockDim.x + threadIdx.x) >> 5);  // matrix id
    if (gw >= B) return;
    int lane = threadIdx.x & 31;
    int tj = lane & 7;        // column group (8 groups of 8 cols)
    int ti = lane >> 3;       // row group    (4 groups of 16 rows)
    int row0 = ti * 16, col0 = tj * 8;

    const float* np = noise + ((size_t)gw * 64 + row0) * 64 + col0;
    const float* gp = d_gp2 + row0 * 64 + col0;
    const float KS = 14.4269504088896341f;     // 10 * log2(e)

    // Frozen kernel matrix tile: 16 rows x 8 cols per lane, 4 f32x2 per row.
    u64 K[16][4];
    float m[16];

    // ---- load, scale into log2 domain, per-row max (in-thread part) ----
    #pragma unroll
    for (int r = 0; r < 16; ++r){
        float4 n0 = *(const float4*)(np + (size_t)r * 64);
        float4 n1 = *(const float4*)(np + (size_t)r * 64 + 4);
        float4 g0 = *(const float4*)(gp + r * 64);
        float4 g1 = *(const float4*)(gp + r * 64 + 4);
        float x0 = fmaf(n0.x, KS, g0.x);
        float x1 = fmaf(n0.y, KS, g0.y);
        float x2 = fmaf(n0.z, KS, g0.z);
        float x3 = fmaf(n0.w, KS, g0.w);
        float x4 = fmaf(n1.x, KS, g1.x);
        float x5 = fmaf(n1.y, KS, g1.y);
        float x6 = fmaf(n1.z, KS, g1.z);
        float x7 = fmaf(n1.w, KS, g1.w);
        K[r][0] = pk2(x0, x1);
        K[r][1] = pk2(x2, x3);
        K[r][2] = pk2(x4, x5);
        K[r][3] = pk2(x6, x7);
        m[r] = fmaxf(fmaxf(fmaxf(x0, x1), fmaxf(x2, x3)),
                     fmaxf(fmaxf(x4, x5), fmaxf(x6, x7)));
    }
    // ---- row max across lanes, K = exp2(la2 - rowmax)  (entries in (0,1]) ----
    #pragma unroll
    for (int r = 0; r < 16; ++r){
        float mm = m[r];
        mm = fmaxf(mm, __shfl_xor_sync(FULLMASK, mm, 1));
        mm = fmaxf(mm, __shfl_xor_sync(FULLMASK, mm, 2));
        mm = fmaxf(mm, __shfl_xor_sync(FULLMASK, mm, 4));
        u64 nm = pk2(-mm, -mm);
        #pragma unroll
        for (int p = 0; p < 4; ++p){
            u64 t = addx2(K[r][p], nm);
            float u, v; up2(t, u, v);
            K[r][p] = pk2(fex2(u), fex2(v));
        }
    }

    // ---- 50 Sinkhorn iterations on scaling vectors only ----
    // c holds this lane's 8 column scales (packed); rv holds 16 row scales.
    u64 c[4];
    c[0] = pk2(1.f, 1.f); c[1] = c[0]; c[2] = c[0]; c[3] = c[0];
    float rv[16];

    #pragma unroll 1
    for (int it = 0; it < 50; ++it){
        // r = 1 / (K c): packed matvec + horizontal + 8-lane butterfly
        #pragma unroll
        for (int rp = 0; rp < 8; ++rp){
            int r0 = 2 * rp, r1 = r0 + 1;
            u64 acc0 = mulx2(K[r0][0], c[0]);
            acc0 = fmax2(K[r0][1], c[1], acc0);
            acc0 = fmax2(K[r0][2], c[2], acc0);
            acc0 = fmax2(K[r0][3], c[3], acc0);
            u64 acc1 = mulx2(K[r1][0], c[0]);
            acc1 = fmax2(K[r1][1], c[1], acc1);
            acc1 = fmax2(K[r1][2], c[2], acc1);
            acc1 = fmax2(K[r1][3], c[3], acc1);
            float a, b, d, e;
            up2(acc0, a, b); up2(acc1, d, e);
            u64 pr = pk2(a + b, d + e);                 // two rows packed
            pr = addx2(pr, shfl64(pr, 1));
            pr = addx2(pr, shfl64(pr, 2));
            pr = addx2(pr, shfl64(pr, 4));
            float rs0, rs1; up2(pr, rs0, rs1);
            rv[r0] = frcp(rs0);
            rv[r1] = frcp(rs1);
        }
        // c = 1 / (K^T r): packed column accumulation + 4-lane butterfly
        u64 rr = pk2(rv[0], rv[0]);
        u64 a0 = mulx2(K[0][0], rr);
        u64 a1 = mulx2(K[0][1], rr);
        u64 a2 = mulx2(K[0][2], rr);
        u64 a3 = mulx2(K[0][3], rr);
        #pragma unroll
        for (int r = 1; r < 16; ++r){
            rr = pk2(rv[r], rv[r]);
            a0 = fmax2(K[r][0], rr, a0);
            a1 = fmax2(K[r][1], rr, a1);
            a2 = fmax2(K[r][2], rr, a2);
            a3 = fmax2(K[r][3], rr, a3);
        }
        a0 = addx2(a0, shfl64(a0, 8));
        a1 = addx2(a1, shfl64(a1, 8));
        a2 = addx2(a2, shfl64(a2, 8));
        a3 = addx2(a3, shfl64(a3, 8));
        a0 = addx2(a0, shfl64(a0, 16));
        a1 = addx2(a1, shfl64(a1, 16));
        a2 = addx2(a2, shfl64(a2, 16));
        a3 = addx2(a3, shfl64(a3, 16));
        float x, y;
        up2(a0, x, y); c[0] = pk2(frcp(x), frcp(y));
        up2(a1, x, y); c[1] = pk2(frcp(x), frcp(y));
        up2(a2, x, y); c[2] = pk2(frcp(x), frcp(y));
        up2(a3, x, y); c[3] = pk2(frcp(x), frcp(y));
    }

    // ---- materialize out = diag(r) K diag(c) and store ----
    float* op = out + ((size_t)gw * 64 + row0) * 64 + col0;
    #pragma unroll
    for (int r = 0; r < 16; ++r){
        u64 rr = pk2(rv[r], rv[r]);
        u64 t0 = mulx2(mulx2(K[r][0], rr), c[0]);
        u64 t1 = mulx2(mulx2(K[r][1], rr), c[1]);
        u64 t2 = mulx2(mulx2(K[r][2], rr), c[2]);
        u64 t3 = mulx2(mulx2(K[r][3], rr), c[3]);
        float x0, x1, x2, x3, x4, x5, x6, x7;
        up2(t0, x0, x1); up2(t1, x2, x3);
        up2(t2, x4, x5); up2(t3, x6, x7);
        *(float4*)(op + (size_t)r * 64)     = make_float4(x0, x1, x2, x3);
        *(float4*)(op + (size_t)r * 64 + 4) = make_float4(x4, x5, x6, x7);
    }
}

extern "C" void kernel_launch(void* const* d_in, const int* in_sizes, int n_in,
                              void* d_out, int out_size) {
    const float* gamma = (const float*)d_in[0];   // [64,64] fp32
    const float* noise = (const float*)d_in[1];   // [B,64,64] fp32
    float* out = (float*)d_out;                   // [B,64,64] fp32
    int B = in_sizes[1] / (64 * 64);

    prep_kernel<<<16, 256>>>(gamma);
    int warps = B;                                 // one warp per matrix
    int blocks = (warps * 32 + 383) / 384;
    sinkhorn_kernel<<<blocks, 384>>>(noise, out, B);
}